// round 13
// baseline (speedup 1.0000x reference)
#include <cuda_runtime.h>
#include <cuda_fp16.h>
#include <math.h>
#include <stdint.h>

#define Bn 16
#define Tn 4096
#define Dn 1024
#define HIDn 1365
#define NPAD 1408
#define ROWS (Bn*Tn)       // 65536
#define NT 11              // N tiles of 128
#define MH_TILES 384       // HMMA m-tiles (rows 0..49151)
#define MS_TILES 128       // SIMT m-tiles (rows 49152..65535)
#define N_HMMA (MH_TILES*NT)   // 4224
#define N_SIMT (MS_TILES*NT)   // 1408
#define N_CTAS (N_HMMA + N_SIMT)

typedef unsigned long long u64;

// ---------------- scratch ----------------
__device__ float g_s[ROWS];
__device__ float g_cb[ROWS];
__device__ float g_Bp[(size_t)NPAD * Dn];   // lnw * w1, padded with zeros
__device__ float g_u[NPAD];
__device__ float g_bb[NPAD];
__device__ float g_w2p[NPAD];
__device__ float g_part[(size_t)NT * ROWS];
__device__ float g_ent[Bn];
__device__ int   g_ticket;

// ---------------- SMEM layout (bytes) ----------------
#define STRDB 48                 // HMMA row stride: 32B data + 16B pad
#define MATB (128 * STRDB)       // 6144 per matrix
#define S_AHI 0
#define S_ALO (MATB)
#define S_BHI (2*MATB)
#define S_BLO (3*MATB)
#define STAGEB (4*MATB)          // 24576
#define S_EPI (2*STAGEB)         // 49152 (128*16B)
#define S_RED (S_EPI + 2048)
#define SMEM_REQ (S_RED + 2048)  // 53248
// SIMT path layout (within same dynamic smem): A 2 stages x 4096B, B likewise
#define SIM_A 0
#define SIM_B 8192

// ---------------- helpers ----------------
__device__ __forceinline__ void sts128(uint32_t addr, uint32_t a, uint32_t b, uint32_t c, uint32_t d) {
    asm volatile("st.shared.v4.b32 [%0], {%1,%2,%3,%4};" :: "r"(addr), "r"(a), "r"(b), "r"(c), "r"(d));
}
__device__ __forceinline__ void stsf(uint32_t addr, float v) {
    asm volatile("st.shared.f32 [%0], %1;" :: "r"(addr), "f"(v));
}
__device__ __forceinline__ float ldsf(uint32_t addr) {
    float v; asm volatile("ld.shared.f32 %0, [%1];" : "=f"(v) : "r"(addr)); return v;
}
__device__ __forceinline__ void lds4f(uint32_t addr, float& a, float& b, float& c, float& d) {
    asm volatile("ld.shared.v4.f32 {%0,%1,%2,%3}, [%4];"
                 : "=f"(a), "=f"(b), "=f"(c), "=f"(d) : "r"(addr));
}
__device__ __forceinline__ void sts4f(uint32_t addr, float a, float b, float c, float d) {
    asm volatile("st.shared.v4.f32 [%0], {%1,%2,%3,%4};"
                 :: "r"(addr), "f"(a), "f"(b), "f"(c), "f"(d));
}
__device__ __forceinline__ void ldsm4(uint32_t r[4], uint32_t addr) {
    asm volatile("ldmatrix.sync.aligned.m8n8.x4.shared.b16 {%0,%1,%2,%3}, [%4];"
                 : "=r"(r[0]), "=r"(r[1]), "=r"(r[2]), "=r"(r[3]) : "r"(addr));
}
__device__ __forceinline__ void mma16(float c[4], const uint32_t a[4], const uint32_t b[2]) {
    asm("mma.sync.aligned.m16n8k16.row.col.f32.f16.f16.f32 "
        "{%0,%1,%2,%3}, {%4,%5,%6,%7}, {%8,%9}, {%0,%1,%2,%3};"
        : "+f"(c[0]), "+f"(c[1]), "+f"(c[2]), "+f"(c[3])
        : "r"(a[0]), "r"(a[1]), "r"(a[2]), "r"(a[3]), "r"(b[0]), "r"(b[1]));
}
__device__ __forceinline__ void split2(float a, float b, uint32_t& hi, uint32_t& lo) {
    __half ha = __float2half_rn(a), hb = __float2half_rn(b);
    float ra = a - __half2float(ha);
    float rb = b - __half2float(hb);
    __half la = __float2half_rn(ra), lb = __float2half_rn(rb);
    hi = (uint32_t)__half_as_ushort(ha) | ((uint32_t)__half_as_ushort(hb) << 16);
    lo = (uint32_t)__half_as_ushort(la) | ((uint32_t)__half_as_ushort(lb) << 16);
}
__device__ __forceinline__ void cvtstore(uint32_t hiAddr, float4 v0, float4 v1) {
    uint32_t h0,h1,h2,h3,l0,l1,l2,l3;
    split2(v0.x, v0.y, h0, l0); split2(v0.z, v0.w, h1, l1);
    split2(v1.x, v1.y, h2, l2); split2(v1.z, v1.w, h3, l3);
    sts128(hiAddr,        h0, h1, h2, h3);
    sts128(hiAddr + MATB, l0, l1, l2, l3);
}
// f32x2 packed helpers (SIMT path)
__device__ __forceinline__ u64 pack2(float x, float y){
    u64 r; asm("mov.b64 %0, {%1, %2};" : "=l"(r) : "f"(x), "f"(y)); return r;
}
__device__ __forceinline__ void unpack2(u64 v, float& x, float& y){
    asm("mov.b64 {%0, %1}, %2;" : "=f"(x), "=f"(y) : "l"(v));
}
__device__ __forceinline__ void ffma2(u64& c, u64 a, u64 b){
    asm("fma.rn.f32x2 %0, %1, %2, %0;" : "+l"(c) : "l"(a), "l"(b));
}

// ---------------- kernel 0: fused stats + prep (round-12) ----------------
__global__ __launch_bounds__(256) void combo_kernel(
    const float* __restrict__ emb, const float* __restrict__ attn,
    const float* __restrict__ w1, const float* __restrict__ b1,
    const float* __restrict__ w2, const float* __restrict__ lnw,
    const float* __restrict__ lnb)
{
    int tid = threadIdx.x;
    if (blockIdx.x == 0 && tid == 0) g_ticket = 0;

    if (blockIdx.x < ROWS / 8) {
        int row = blockIdx.x * 8 + (tid >> 5);
        int lane = tid & 31;
        const float4* p = (const float4*)(emb + (size_t)row * Dn);
        float a = attn[row];
        float s = 0.f, q = 0.f;
#pragma unroll
        for (int i = 0; i < 8; ++i) {
            float4 v = p[lane + 32 * i];
            v.x *= a; v.y *= a; v.z *= a; v.w *= a;
            s += v.x + v.y + v.z + v.w;
            q += v.x*v.x + v.y*v.y + v.z*v.z + v.w*v.w;
        }
#pragma unroll
        for (int o = 16; o > 0; o >>= 1) {
            s += __shfl_xor_sync(0xffffffffu, s, o);
            q += __shfl_xor_sync(0xffffffffu, q, o);
        }
        if (lane == 0) {
            float mu  = s * (1.f / Dn);
            float var = fmaxf(q * (1.f / Dn) - mu * mu, 0.f);
            float rs  = rsqrtf(var + 1e-5f);
            g_s[row]  = a * rs;
            g_cb[row] = -mu * rs;
        }
    } else {
        __shared__ float ru[8], rv[8];
        int n = blockIdx.x - ROWS / 8;
        if (n < HIDn) {
            float4 w  = ((const float4*)(w1 + (size_t)n * Dn))[tid];
            float4 lw = ((const float4*)lnw)[tid];
            float4 lb = ((const float4*)lnb)[tid];
            float4 bp;
            bp.x = lw.x * w.x; bp.y = lw.y * w.y; bp.z = lw.z * w.z; bp.w = lw.w * w.w;
            ((float4*)(g_Bp + (size_t)n * Dn))[tid] = bp;
            float up = bp.x + bp.y + bp.z + bp.w;
            float vp = lb.x*w.x + lb.y*w.y + lb.z*w.z + lb.w*w.w;
#pragma unroll
            for (int o = 16; o > 0; o >>= 1) {
                up += __shfl_xor_sync(0xffffffffu, up, o);
                vp += __shfl_xor_sync(0xffffffffu, vp, o);
            }
            if ((tid & 31) == 0) { ru[tid >> 5] = up; rv[tid >> 5] = vp; }
            __syncthreads();
            if (tid == 0) {
                float u = 0.f, v = 0.f;
#pragma unroll
                for (int i = 0; i < 8; ++i) { u += ru[i]; v += rv[i]; }
                g_u[n]   = u;
                g_bb[n]  = b1[n] + v;
                g_w2p[n] = w2[n];
            }
        } else {
            ((float4*)(g_Bp + (size_t)n * Dn))[tid] = make_float4(0.f, 0.f, 0.f, 0.f);
            if (tid == 0) { g_u[n] = 0.f; g_bb[n] = 0.f; g_w2p[n] = 0.f; }
        }
    }
}

// ---------------- kernel 1: heterogeneous megakernel ----------------
__global__ __launch_bounds__(256, 2) void mega_kernel(const float* __restrict__ emb)
{
    extern __shared__ char smraw[];
    uint32_t sb = (uint32_t)__cvta_generic_to_shared(smraw);
    int bid = blockIdx.x;
    int tid = threadIdx.x;
    const float GC = 0.70710678118654752440f;

    if ((bid & 3) == 0) {
        // ================= SIMT FFMA2 path (1408 CTAs, 128 m-tiles) =================
        int s_id = bid >> 2;
        int m0 = (MH_TILES + s_id / NT) * 128;
        int n0 = (s_id % NT) * 128;

        int lrow = tid >> 1;
        int k4   = (tid & 1) << 2;
        const float* aptr = emb  + (size_t)(m0 + lrow) * Dn + k4;
        const float* bptr = g_Bp + (size_t)(n0 + lrow) * Dn + k4;

        int tx = tid & 15;
        int ty = tid >> 4;

        u64 acc[8][4];
#pragma unroll
        for (int i = 0; i < 8; ++i)
#pragma unroll
            for (int j = 0; j < 4; ++j) acc[i][j] = 0ull;

        // prologue: stage 0
        float4 av = *(const float4*)(aptr);
        float4 bv = *(const float4*)(bptr);
#pragma unroll
        for (int i = 0; i < 4; ++i) {
            stsf(sb + SIM_A + (uint32_t)((k4 + i) * 128 + lrow) * 4, ((const float*)&av)[i]);
            stsf(sb + SIM_B + (uint32_t)((k4 + i) * 128 + lrow) * 4, ((const float*)&bv)[i]);
        }
        __syncthreads();

        for (int it = 0; it < 128; ++it) {
            uint32_t bufo = (uint32_t)(it & 1) * 4096u;
            if (it < 127) {
                int k0 = (it + 1) * 8;
                av = *(const float4*)(aptr + k0);
                bv = *(const float4*)(bptr + k0);
            }
#pragma unroll
            for (int k = 0; k < 8; ++k) {
                float a0x,a0y,a0z,a0w, a1x,a1y,a1z,a1w;
                float b0x,b0y,b0z,b0w, b1x,b1y,b1z,b1w;
                lds4f(sb + SIM_A + bufo + (uint32_t)(k * 128 + ty * 4) * 4,      a0x,a0y,a0z,a0w);
                lds4f(sb + SIM_A + bufo + (uint32_t)(k * 128 + 64 + ty * 4) * 4, a1x,a1y,a1z,a1w);
                lds4f(sb + SIM_B + bufo + (uint32_t)(k * 128 + tx * 4) * 4,      b0x,b0y,b0z,b0w);
                lds4f(sb + SIM_B + bufo + (uint32_t)(k * 128 + 64 + tx * 4) * 4, b1x,b1y,b1z,b1w);
                u64 B0 = pack2(b0x, b0y);
                u64 B1 = pack2(b0z, b0w);
                u64 B2 = pack2(b1x, b1y);
                u64 B3 = pack2(b1z, b1w);
                float as8[8] = {a0x,a0y,a0z,a0w, a1x,a1y,a1z,a1w};
#pragma unroll
                for (int mi = 0; mi < 8; ++mi) {
                    u64 A = pack2(as8[mi], as8[mi]);
                    ffma2(acc[mi][0], A, B0);
                    ffma2(acc[mi][1], A, B1);
                    ffma2(acc[mi][2], A, B2);
                    ffma2(acc[mi][3], A, B3);
                }
            }
            if (it < 127) {
                uint32_t nbo = (uint32_t)((it + 1) & 1) * 4096u;
#pragma unroll
                for (int i = 0; i < 4; ++i) {
                    stsf(sb + SIM_A + nbo + (uint32_t)((k4 + i) * 128 + lrow) * 4, ((const float*)&av)[i]);
                    stsf(sb + SIM_B + nbo + (uint32_t)((k4 + i) * 128 + lrow) * 4, ((const float*)&bv)[i]);
                }
                __syncthreads();
            }
        }

        // epilogue: x = s*acc + cb*u + bb -> gelu -> *w2 -> reduce
        float uu[8], bbv[8], w2v[8];
#pragma unroll
        for (int j = 0; j < 8; ++j) {
            int hl = (j < 4) ? (tx * 4 + j) : (64 + tx * 4 + (j - 4));
            int n = n0 + hl;
            uu[j] = g_u[n]; bbv[j] = g_bb[n]; w2v[j] = g_w2p[n];
        }
        float part[8];
#pragma unroll
        for (int mi = 0; mi < 8; ++mi) {
            int ml = (mi < 4) ? (ty * 4 + mi) : (64 + ty * 4 + (mi - 4));
            float sm_ = g_s[m0 + ml], cbm = g_cb[m0 + ml];
            float sum = 0.f;
#pragma unroll
            for (int p = 0; p < 4; ++p) {
                float c0, c1; unpack2(acc[mi][p], c0, c1);
                int j0 = p * 2, j1 = p * 2 + 1;
                float x0 = fmaf(sm_, c0, fmaf(cbm, uu[j0], bbv[j0]));
                float x1 = fmaf(sm_, c1, fmaf(cbm, uu[j1], bbv[j1]));
                sum = fmaf(0.5f * x0 * (1.f + erff(x0 * GC)), w2v[j0], sum);
                sum = fmaf(0.5f * x1 * (1.f + erff(x1 * GC)), w2v[j1], sum);
            }
            part[mi] = sum;
        }
        __syncthreads();
#pragma unroll
        for (int mi = 0; mi < 8; ++mi) {
            int ml = (mi < 4) ? (ty * 4 + mi) : (64 + ty * 4 + (mi - 4));
            stsf(sb + (uint32_t)(ml * 16 + tx) * 4, part[mi]);
        }
        __syncthreads();
        if (tid < 128) {
            float srow = 0.f;
#pragma unroll
            for (int i = 0; i < 16; ++i) srow += ldsf(sb + (uint32_t)(tid * 16 + i) * 4);
            g_part[(size_t)(s_id % NT) * ROWS + m0 + tid] = srow;
        }
        return;
    }

    // ================= HMMA fp16x3 path (4224 CTAs, 384 m-tiles; round-12 core) =================
    int h_id = bid - ((bid >> 2) + 1);
    int m0  = (h_id / NT) * 128;
    int n0  = (h_id % NT) * 128;

    int wid = tid >> 5;
    int l   = tid & 31;
    int wm  = (wid >> 2) * 64;
    int wn  = (wid & 3) * 32;

    int lrow = tid >> 1;
    int lc   = tid & 1;
    const float* aP = emb  + (size_t)(m0 + lrow) * Dn + lc * 8;
    const float* bP = g_Bp + (size_t)(n0 + lrow) * Dn + lc * 8;
    uint32_t sA = sb + S_AHI + (uint32_t)lrow * STRDB + (uint32_t)lc * 16;
    uint32_t sB = sb + S_BHI + (uint32_t)lrow * STRDB + (uint32_t)lc * 16;

    int g = l >> 3, j = l & 7;
    uint32_t aAddr0 = sb + S_AHI
        + (uint32_t)(wm + ((g & 1) ? 8 : 0) + j) * STRDB + (uint32_t)(g >> 1) * 16;
    uint32_t bAddr0 = sb + S_BHI
        + (uint32_t)(wn + ((g >> 1) ? 8 : 0) + j) * STRDB + (uint32_t)(g & 1) * 16;

    float acc[4][4][4];
#pragma unroll
    for (int mi = 0; mi < 4; ++mi)
#pragma unroll
        for (int nf = 0; nf < 4; ++nf)
#pragma unroll
            for (int e = 0; e < 4; ++e) acc[mi][nf][e] = 0.f;

    float4 pa0 = ((const float4*)aP)[0], pa1 = ((const float4*)aP)[1];
    float4 pb0 = ((const float4*)bP)[0], pb1 = ((const float4*)bP)[1];
    cvtstore(sA, pa0, pa1);
    cvtstore(sB, pb0, pb1);
    __syncthreads();

    for (int it = 0; it < 64; ++it) {
        uint32_t so = (uint32_t)(it & 1) * STAGEB;
        if (it < 63) {
            int kc = (it + 1) * 16;
            pa0 = ((const float4*)(aP + kc))[0]; pa1 = ((const float4*)(aP + kc))[1];
            pb0 = ((const float4*)(bP + kc))[0]; pb1 = ((const float4*)(bP + kc))[1];
        }
        uint32_t bh[4][2], bl[4][2];
#pragma unroll
        for (int p = 0; p < 2; ++p) {
            uint32_t r[4];
            uint32_t ba = bAddr0 + (uint32_t)p * (16 * STRDB) + so;
            ldsm4(r, ba);
            bh[2*p][0] = r[0]; bh[2*p][1] = r[1]; bh[2*p+1][0] = r[2]; bh[2*p+1][1] = r[3];
            ldsm4(r, ba + MATB);
            bl[2*p][0] = r[0]; bl[2*p][1] = r[1]; bl[2*p+1][0] = r[2]; bl[2*p+1][1] = r[3];
        }
#pragma unroll
        for (int mi = 0; mi < 4; ++mi) {
            uint32_t ah[4], al[4];
            uint32_t aa = aAddr0 + (uint32_t)mi * (16 * STRDB) + so;
            ldsm4(ah, aa);
            ldsm4(al, aa + MATB);
#pragma unroll
            for (int nf = 0; nf < 4; ++nf) mma16(acc[mi][nf], ah, bh[nf]);
#pragma unroll
            for (int nf = 0; nf < 4; ++nf) mma16(acc[mi][nf], al, bh[nf]);
#pragma unroll
            for (int nf = 0; nf < 4; ++nf) mma16(acc[mi][nf], ah, bl[nf]);
        }
        if (it < 63) {
            uint32_t ns = (uint32_t)((it + 1) & 1) * STAGEB;
            cvtstore(sA + ns, pa0, pa1);
            cvtstore(sB + ns, pb0, pb1);
        }
        __syncthreads();
    }

    if (tid < 128) {
        int n = n0 + tid;
        sts4f(sb + S_EPI + (uint32_t)tid * 16, g_u[n], g_bb[n], g_w2p[n], 0.f);
    }
    __syncthreads();

    int lg = l >> 2;
    int lt = l & 3;

    float uu[8], bbv[8], w2v[8];
#pragma unroll
    for (int nf = 0; nf < 4; ++nf) {
#pragma unroll
        for (int e = 0; e < 2; ++e) {
            int nl = wn + nf * 8 + 2 * lt + e;
            float pad;
            lds4f(sb + S_EPI + (uint32_t)nl * 16, uu[nf*2+e], bbv[nf*2+e], w2v[nf*2+e], pad);
        }
    }

#pragma unroll
    for (int mi = 0; mi < 4; ++mi) {
        int r0 = wm + mi * 16 + lg;
        int r1 = r0 + 8;
        float s0 = g_s[m0 + r0], c0 = g_cb[m0 + r0];
        float s1 = g_s[m0 + r1], c1 = g_cb[m0 + r1];
        float sum0 = 0.f, sum1 = 0.f;
#pragma unroll
        for (int nf = 0; nf < 4; ++nf) {
#pragma unroll
            for (int e = 0; e < 2; ++e) {
                int jj = nf * 2 + e;
                float x0 = fmaf(s0, acc[mi][nf][e],     fmaf(c0, uu[jj], bbv[jj]));
                float x1 = fmaf(s1, acc[mi][nf][e + 2], fmaf(c1, uu[jj], bbv[jj]));
                float gl0 = 0.5f * x0 * (1.f + erff(x0 * GC));
                float gl1 = 0.5f * x1 * (1.f + erff(x1 * GC));
                sum0 = fmaf(gl0, w2v[jj], sum0);
                sum1 = fmaf(gl1, w2v[jj], sum1);
            }
        }
        sum0 += __shfl_xor_sync(0xffffffffu, sum0, 1);
        sum0 += __shfl_xor_sync(0xffffffffu, sum0, 2);
        sum1 += __shfl_xor_sync(0xffffffffu, sum1, 1);
        sum1 += __shfl_xor_sync(0xffffffffu, sum1, 2);
        if (lt == 0) {
            stsf(sb + S_RED + (uint32_t)(r0 * 4 + (wid & 3)) * 4, sum0);
            stsf(sb + S_RED + (uint32_t)(r1 * 4 + (wid & 3)) * 4, sum1);
        }
    }
    __syncthreads();
    if (tid < 128) {
        uint32_t ra = sb + S_RED + (uint32_t)tid * 16;
        float a, b, c, d; lds4f(ra, a, b, c, d);
        g_part[(size_t)(h_id % NT) * ROWS + m0 + tid] = ((a + b) + c) + d;
    }
}

// ---------------- kernel 2: fused reduce + softmax/entropy/K/z + radix top-K (round-12) ----------------
__global__ __launch_bounds__(1024) void final_kernel(
    const float* __restrict__ attn, const float* __restrict__ fc2_b,
    float* __restrict__ out)
{
    __shared__ float sbuf[1024];
    __shared__ uint32_t zbits[Tn];
    __shared__ uint32_t hist[256];
    __shared__ uint32_t bcast[2];
    __shared__ uint32_t scanbuf[1024];
    int b = blockIdx.x, tid = threadIdx.x;
    float base = fc2_b[0];

    float sv[4], a[4], sm[4];
#pragma unroll
    for (int i = 0; i < 4; ++i) {
        int t = tid + 1024 * i;
        float s = base;
#pragma unroll
        for (int nt = 0; nt < NT; ++nt) s += g_part[(size_t)nt * ROWS + b * Tn + t];
        sv[i] = s;
        a[i]  = attn[b * Tn + t];
        sm[i] = (a[i] == 0.f) ? -1e9f : sv[i];
    }
    sbuf[tid] = a[0] + a[1] + a[2] + a[3]; __syncthreads();
    for (int o = 512; o > 0; o >>= 1) { if (tid < o) sbuf[tid] += sbuf[tid + o]; __syncthreads(); }
    float Teff = sbuf[0]; __syncthreads();
    sbuf[tid] = fmaxf(fmaxf(sm[0], sm[1]), fmaxf(sm[2], sm[3])); __syncthreads();
    for (int o = 512; o > 0; o >>= 1) { if (tid < o) sbuf[tid] = fmaxf(sbuf[tid], sbuf[tid + o]); __syncthreads(); }
    float M = sbuf[0]; __syncthreads();
    float e[4]; float es = 0.f;
#pragma unroll
    for (int i = 0; i < 4; ++i) { e[i] = expf(sm[i] - M); es += e[i]; }
    sbuf[tid] = es; __syncthreads();
    for (int o = 512; o > 0; o >>= 1) { if (tid < o) sbuf[tid] += sbuf[tid + o]; __syncthreads(); }
    float Z = sbuf[0]; __syncthreads();

    float K = fmaxf(1.f, rintf(0.2f * Teff));
    float entl = 0.f;
#pragma unroll
    for (int i = 0; i < 4; ++i) {
        int t = tid + 1024 * i;
        float p = e[i] / Z;
        float z = K * p;
        out[ROWS + b * Tn + t] = z;
        zbits[t] = __float_as_uint(z);
        entl -= p * logf(p + 1e-12f);
    }
    sbuf[tid] = entl; __syncthreads();
    for (int o = 512; o > 0; o >>= 1) { if (tid < o) sbuf[tid] += sbuf[tid + o]; __syncthreads(); }
    if (tid == 0) g_ent[b] = sbuf[0] / logf(fmaxf(Teff, 1.f));
    __syncthreads();

    uint32_t Ki = (uint32_t)K;
    uint32_t prefix = 0, mask = 0, krem = Ki;
#pragma unroll
    for (int lvl = 3; lvl >= 0; --lvl) {
        if (tid < 256) hist[tid] = 0;
        __syncthreads();
        int sh = lvl * 8;
#pragma unroll
        for (int i = 0; i < 4; ++i) {
            uint32_t v = zbits[tid + 1024 * i];
            if ((v & mask) == prefix) atomicAdd(&hist[(v >> sh) & 255u], 1u);
        }
        __syncthreads();
        if (tid == 0) {
            uint32_t acc = 0; int d = 255;
            for (; d > 0; --d) { if (acc + hist[d] >= krem) break; acc += hist[d]; }
            bcast[0] = (uint32_t)d; bcast[1] = krem - acc;
        }
        __syncthreads();
        uint32_t d = bcast[0]; krem = bcast[1];
        prefix |= d << sh; mask |= 255u << sh;
        __syncthreads();
    }
    uint32_t v = prefix;

    uint32_t ev[4]; uint32_t eqc = 0;
#pragma unroll
    for (int jj = 0; jj < 4; ++jj) { ev[jj] = zbits[tid * 4 + jj]; eqc += (ev[jj] == v); }
    scanbuf[tid] = eqc; __syncthreads();
    for (int o = 1; o < 1024; o <<= 1) {
        uint32_t t = (tid >= o) ? scanbuf[tid - o] : 0u;
        __syncthreads();
        scanbuf[tid] += t;
        __syncthreads();
    }
    uint32_t run = scanbuf[tid] - eqc;

    float* dst = out + (size_t)b * Tn;
#pragma unroll
    for (int jj = 0; jj < 4; ++jj) {
        uint32_t z = ev[jj];
        bool h = (z > v) || (z == v && run < krem);
        run += (z == v);
        dst[tid * 4 + jj] = h ? 1.f : 0.f;
    }

    if (tid == 0) {
        __threadfence();
        int t = atomicAdd(&g_ticket, 1);
        if (t == Bn - 1) {
            float s = 0.f;
#pragma unroll
            for (int i = 0; i < Bn; ++i) s += g_ent[i];
            out[2 * ROWS] = s * (1.f / Bn);
        }
    }
}

// ---------------- launch ----------------
extern "C" void kernel_launch(void* const* d_in, const int* in_sizes, int n_in,
                              void* d_out, int out_size)
{
    const float* emb  = (const float*)d_in[0];
    const float* attn = (const float*)d_in[1];
    const float* lnw  = (const float*)d_in[2];
    const float* lnb  = (const float*)d_in[3];
    const float* w1   = (const float*)d_in[4];
    const float* b1   = (const float*)d_in[5];
    const float* w2   = (const float*)d_in[6];
    const float* b2   = (const float*)d_in[7];
    float* out = (float*)d_out;

    static int smem_set = 0;
    if (!smem_set) {
        cudaFuncSetAttribute(mega_kernel, cudaFuncAttributeMaxDynamicSharedMemorySize, SMEM_REQ);
        smem_set = 1;
    }

    combo_kernel<<<ROWS / 8 + NPAD, 256>>>(emb, attn, w1, b1, w2, lnw, lnb);
    mega_kernel<<<N_CTAS, 256, SMEM_REQ>>>(emb);
    final_kernel<<<Bn, 1024>>>(attn, b2, out);
}

// round 14
// speedup vs baseline: 1.3333x; 1.3333x over previous
#include <cuda_runtime.h>
#include <cuda_fp16.h>
#include <math.h>
#include <stdint.h>

#define Bn 16
#define Tn 4096
#define Dn 1024
#define HIDn 1365
#define NPAD 1408
#define ROWS (Bn*Tn)       // 65536
#define NT 11              // N tiles of 128

// ---------------- scratch ----------------
__device__ float g_s[ROWS];
__device__ float g_cb[ROWS];
__device__ float g_Bp[(size_t)NPAD * Dn];   // lnw * w1, padded with zeros
__device__ float g_u[NPAD];
__device__ float g_bb[NPAD];
__device__ float g_w2p[NPAD];
__device__ float g_part[(size_t)NT * ROWS];
__device__ float g_ent[Bn];
__device__ int   g_ticket;

// ---------------- SMEM layout (bytes) ----------------
#define STRDB 48                 // row stride: 32B data (16 halves) + 16B pad
#define MATB (128 * STRDB)       // 6144 per matrix
#define S_AHI 0
#define S_ALO (MATB)
#define S_BHI (2*MATB)
#define S_BLO (3*MATB)
#define STAGEB (4*MATB)          // 24576
#define S_EPI (2*STAGEB)         // 49152 (128*16B)
#define S_RED (S_EPI + 2048)
#define SMEM_REQ (S_RED + 2048)  // 53248

// ---------------- helpers ----------------
__device__ __forceinline__ void sts128(uint32_t addr, uint32_t a, uint32_t b, uint32_t c, uint32_t d) {
    asm volatile("st.shared.v4.b32 [%0], {%1,%2,%3,%4};" :: "r"(addr), "r"(a), "r"(b), "r"(c), "r"(d));
}
__device__ __forceinline__ void stsf(uint32_t addr, float v) {
    asm volatile("st.shared.f32 [%0], %1;" :: "r"(addr), "f"(v));
}
__device__ __forceinline__ void lds4f(uint32_t addr, float& a, float& b, float& c, float& d) {
    asm volatile("ld.shared.v4.f32 {%0,%1,%2,%3}, [%4];"
                 : "=f"(a), "=f"(b), "=f"(c), "=f"(d) : "r"(addr));
}
__device__ __forceinline__ void sts4f(uint32_t addr, float a, float b, float c, float d) {
    asm volatile("st.shared.v4.f32 [%0], {%1,%2,%3,%4};"
                 :: "r"(addr), "f"(a), "f"(b), "f"(c), "f"(d));
}
__device__ __forceinline__ void ldsm4(uint32_t r[4], uint32_t addr) {
    asm volatile("ldmatrix.sync.aligned.m8n8.x4.shared.b16 {%0,%1,%2,%3}, [%4];"
                 : "=r"(r[0]), "=r"(r[1]), "=r"(r[2]), "=r"(r[3]) : "r"(addr));
}
__device__ __forceinline__ void mma16(float c[4], const uint32_t a[4], const uint32_t b[2]) {
    asm("mma.sync.aligned.m16n8k16.row.col.f32.f16.f16.f32 "
        "{%0,%1,%2,%3}, {%4,%5,%6,%7}, {%8,%9}, {%0,%1,%2,%3};"
        : "+f"(c[0]), "+f"(c[1]), "+f"(c[2]), "+f"(c[3])
        : "r"(a[0]), "r"(a[1]), "r"(a[2]), "r"(a[3]), "r"(b[0]), "r"(b[1]));
}
// split two floats into packed fp16 hi pair + lo pair
__device__ __forceinline__ void split2(float a, float b, uint32_t& hi, uint32_t& lo) {
    __half ha = __float2half_rn(a), hb = __float2half_rn(b);
    float ra = a - __half2float(ha);
    float rb = b - __half2float(hb);
    __half la = __float2half_rn(ra), lb = __float2half_rn(rb);
    hi = (uint32_t)__half_as_ushort(ha) | ((uint32_t)__half_as_ushort(hb) << 16);
    lo = (uint32_t)__half_as_ushort(la) | ((uint32_t)__half_as_ushort(lb) << 16);
}
// convert 8 floats (one 16B chunk of one row) -> hi sts128 + lo sts128 (lo at +MATB)
__device__ __forceinline__ void cvtstore(uint32_t hiAddr, float4 v0, float4 v1) {
    uint32_t h0,h1,h2,h3,l0,l1,l2,l3;
    split2(v0.x, v0.y, h0, l0); split2(v0.z, v0.w, h1, l1);
    split2(v1.x, v1.y, h2, l2); split2(v1.z, v1.w, h3, l3);
    sts128(hiAddr,        h0, h1, h2, h3);
    sts128(hiAddr + MATB, l0, l1, l2, l3);
}

// ---------------- kernel 0: fused stats (blocks 0..8191) + prep (blocks 8192..9599) ----------------
__global__ __launch_bounds__(256) void combo_kernel(
    const float* __restrict__ emb, const float* __restrict__ attn,
    const float* __restrict__ w1, const float* __restrict__ b1,
    const float* __restrict__ w2, const float* __restrict__ lnw,
    const float* __restrict__ lnb)
{
    int tid = threadIdx.x;
    if (blockIdx.x == 0 && tid == 0) g_ticket = 0;

    if (blockIdx.x < ROWS / 8) {
        int row = blockIdx.x * 8 + (tid >> 5);
        int lane = tid & 31;
        const float4* p = (const float4*)(emb + (size_t)row * Dn);
        float a = attn[row];
        float s = 0.f, q = 0.f;
#pragma unroll
        for (int i = 0; i < 8; ++i) {
            float4 v = p[lane + 32 * i];
            v.x *= a; v.y *= a; v.z *= a; v.w *= a;
            s += v.x + v.y + v.z + v.w;
            q += v.x*v.x + v.y*v.y + v.z*v.z + v.w*v.w;
        }
#pragma unroll
        for (int o = 16; o > 0; o >>= 1) {
            s += __shfl_xor_sync(0xffffffffu, s, o);
            q += __shfl_xor_sync(0xffffffffu, q, o);
        }
        if (lane == 0) {
            float mu  = s * (1.f / Dn);
            float var = fmaxf(q * (1.f / Dn) - mu * mu, 0.f);
            float rs  = rsqrtf(var + 1e-5f);
            g_s[row]  = a * rs;
            g_cb[row] = -mu * rs;
        }
    } else {
        __shared__ float ru[8], rv[8];
        int n = blockIdx.x - ROWS / 8;
        if (n < HIDn) {
            float4 w  = ((const float4*)(w1 + (size_t)n * Dn))[tid];
            float4 lw = ((const float4*)lnw)[tid];
            float4 lb = ((const float4*)lnb)[tid];
            float4 bp;
            bp.x = lw.x * w.x; bp.y = lw.y * w.y; bp.z = lw.z * w.z; bp.w = lw.w * w.w;
            ((float4*)(g_Bp + (size_t)n * Dn))[tid] = bp;
            float up = bp.x + bp.y + bp.z + bp.w;
            float vp = lb.x*w.x + lb.y*w.y + lb.z*w.z + lb.w*w.w;
#pragma unroll
            for (int o = 16; o > 0; o >>= 1) {
                up += __shfl_xor_sync(0xffffffffu, up, o);
                vp += __shfl_xor_sync(0xffffffffu, vp, o);
            }
            if ((tid & 31) == 0) { ru[tid >> 5] = up; rv[tid >> 5] = vp; }
            __syncthreads();
            if (tid == 0) {
                float u = 0.f, v = 0.f;
#pragma unroll
                for (int i = 0; i < 8; ++i) { u += ru[i]; v += rv[i]; }
                g_u[n]   = u;
                g_bb[n]  = b1[n] + v;
                g_w2p[n] = w2[n];
            }
        } else {
            ((float4*)(g_Bp + (size_t)n * Dn))[tid] = make_float4(0.f, 0.f, 0.f, 0.f);
            if (tid == 0) { g_u[n] = 0.f; g_bb[n] = 0.f; g_w2p[n] = 0.f; }
        }
    }
}

// ---------------- kernel 1: fp16x3 mma.sync GEMM (round-12 exact) ----------------
__global__ __launch_bounds__(256, 2) void gemm_kernel(const float* __restrict__ emb)
{
    extern __shared__ char smraw[];
    uint32_t sb = (uint32_t)__cvta_generic_to_shared(smraw);

    int tid = threadIdx.x;
    int wid = tid >> 5;
    int l   = tid & 31;
    int m0  = blockIdx.y * 128;
    int n0  = blockIdx.x * 128;
    int wm  = (wid >> 2) * 64;       // 0 or 64
    int wn  = (wid & 3) * 32;        // 0,32,64,96

    int lrow = tid >> 1;
    int lc   = tid & 1;
    const float* aP = emb  + (size_t)(m0 + lrow) * Dn + lc * 8;
    const float* bP = g_Bp + (size_t)(n0 + lrow) * Dn + lc * 8;
    uint32_t sA = sb + S_AHI + (uint32_t)lrow * STRDB + (uint32_t)lc * 16;
    uint32_t sB = sb + S_BHI + (uint32_t)lrow * STRDB + (uint32_t)lc * 16;

    int g = l >> 3, j = l & 7;
    uint32_t aAddr0 = sb + S_AHI
        + (uint32_t)(wm + ((g & 1) ? 8 : 0) + j) * STRDB + (uint32_t)(g >> 1) * 16;
    uint32_t bAddr0 = sb + S_BHI
        + (uint32_t)(wn + ((g >> 1) ? 8 : 0) + j) * STRDB + (uint32_t)(g & 1) * 16;

    float acc[4][4][4];
#pragma unroll
    for (int mi = 0; mi < 4; ++mi)
#pragma unroll
        for (int nf = 0; nf < 4; ++nf)
#pragma unroll
            for (int e = 0; e < 4; ++e) acc[mi][nf][e] = 0.f;

    float4 pa0 = ((const float4*)aP)[0], pa1 = ((const float4*)aP)[1];
    float4 pb0 = ((const float4*)bP)[0], pb1 = ((const float4*)bP)[1];
    cvtstore(sA, pa0, pa1);
    cvtstore(sB, pb0, pb1);
    __syncthreads();

    for (int it = 0; it < 64; ++it) {
        uint32_t so = (uint32_t)(it & 1) * STAGEB;
        if (it < 63) {
            int kc = (it + 1) * 16;
            pa0 = ((const float4*)(aP + kc))[0]; pa1 = ((const float4*)(aP + kc))[1];
            pb0 = ((const float4*)(bP + kc))[0]; pb1 = ((const float4*)(bP + kc))[1];
        }
        uint32_t bh[4][2], bl[4][2];
#pragma unroll
        for (int p = 0; p < 2; ++p) {
            uint32_t r[4];
            uint32_t ba = bAddr0 + (uint32_t)p * (16 * STRDB) + so;
            ldsm4(r, ba);
            bh[2*p][0] = r[0]; bh[2*p][1] = r[1]; bh[2*p+1][0] = r[2]; bh[2*p+1][1] = r[3];
            ldsm4(r, ba + MATB);
            bl[2*p][0] = r[0]; bl[2*p][1] = r[1]; bl[2*p+1][0] = r[2]; bl[2*p+1][1] = r[3];
        }
#pragma unroll
        for (int mi = 0; mi < 4; ++mi) {
            uint32_t ah[4], al[4];
            uint32_t aa = aAddr0 + (uint32_t)mi * (16 * STRDB) + so;
            ldsm4(ah, aa);
            ldsm4(al, aa + MATB);
#pragma unroll
            for (int nf = 0; nf < 4; ++nf) mma16(acc[mi][nf], ah, bh[nf]);
#pragma unroll
            for (int nf = 0; nf < 4; ++nf) mma16(acc[mi][nf], al, bh[nf]);
#pragma unroll
            for (int nf = 0; nf < 4; ++nf) mma16(acc[mi][nf], ah, bl[nf]);
        }
        if (it < 63) {
            uint32_t ns = (uint32_t)((it + 1) & 1) * STAGEB;
            cvtstore(sA + ns, pa0, pa1);
            cvtstore(sB + ns, pb0, pb1);
        }
        __syncthreads();
    }

    if (tid < 128) {
        int n = n0 + tid;
        sts4f(sb + S_EPI + (uint32_t)tid * 16, g_u[n], g_bb[n], g_w2p[n], 0.f);
    }
    __syncthreads();

    int lg = l >> 2;
    int lt = l & 3;

    float uu[8], bbv[8], w2v[8];
#pragma unroll
    for (int nf = 0; nf < 4; ++nf) {
#pragma unroll
        for (int e = 0; e < 2; ++e) {
            int nl = wn + nf * 8 + 2 * lt + e;
            float pad;
            lds4f(sb + S_EPI + (uint32_t)nl * 16, uu[nf*2+e], bbv[nf*2+e], w2v[nf*2+e], pad);
        }
    }

    const float GC = 0.70710678118654752440f;
#pragma unroll
    for (int mi = 0; mi < 4; ++mi) {
        int r0 = wm + mi * 16 + lg;
        int r1 = r0 + 8;
        float s0 = g_s[m0 + r0], c0 = g_cb[m0 + r0];
        float s1 = g_s[m0 + r1], c1 = g_cb[m0 + r1];
        float sum0 = 0.f, sum1 = 0.f;
#pragma unroll
        for (int nf = 0; nf < 4; ++nf) {
#pragma unroll
            for (int e = 0; e < 2; ++e) {
                int jj = nf * 2 + e;
                float x0 = fmaf(s0, acc[mi][nf][e],     fmaf(c0, uu[jj], bbv[jj]));
                float x1 = fmaf(s1, acc[mi][nf][e + 2], fmaf(c1, uu[jj], bbv[jj]));
                float gl0 = 0.5f * x0 * (1.f + erff(x0 * GC));
                float gl1 = 0.5f * x1 * (1.f + erff(x1 * GC));
                sum0 = fmaf(gl0, w2v[jj], sum0);
                sum1 = fmaf(gl1, w2v[jj], sum1);
            }
        }
        sum0 += __shfl_xor_sync(0xffffffffu, sum0, 1);
        sum0 += __shfl_xor_sync(0xffffffffu, sum0, 2);
        sum1 += __shfl_xor_sync(0xffffffffu, sum1, 1);
        sum1 += __shfl_xor_sync(0xffffffffu, sum1, 2);
        if (lt == 0) {
            stsf(sb + S_RED + (uint32_t)(r0 * 4 + (wid & 3)) * 4, sum0);
            stsf(sb + S_RED + (uint32_t)(r1 * 4 + (wid & 3)) * 4, sum1);
        }
    }
    __syncthreads();
    if (tid < 128) {
        uint32_t ra = sb + S_RED + (uint32_t)tid * 16;
        float a, b, c, d; lds4f(ra, a, b, c, d);
        g_part[(size_t)blockIdx.x * ROWS + m0 + tid] = ((a + b) + c) + d;
    }
}

// ---------------- kernel 2: reduce + softmax/entropy/K/z + radix top-K (warp-optimized) ----------------
__global__ __launch_bounds__(1024) void final_kernel(
    const float* __restrict__ attn, const float* __restrict__ fc2_b,
    float* __restrict__ out)
{
    __shared__ float red[33];
    __shared__ uint32_t zbits[Tn];
    __shared__ uint32_t hist[256];
    __shared__ uint32_t bcast[2];
    __shared__ uint32_t iscan[32];
    int b = blockIdx.x, tid = threadIdx.x;
    int lane = tid & 31, wrp = tid >> 5;
    float base = fc2_b[0];

    float a[4], sm[4];
#pragma unroll
    for (int i = 0; i < 4; ++i) {
        int t = tid + 1024 * i;
        float s = base;
#pragma unroll
        for (int nt = 0; nt < NT; ++nt) s += g_part[(size_t)nt * ROWS + b * Tn + t];
        a[i]  = attn[b * Tn + t];
        sm[i] = (a[i] == 0.f) ? -1e9f : s;
    }

    // --- Teff: block sum via warp shuffles (exact: integer-valued) ---
    float v = a[0] + a[1] + a[2] + a[3];
#pragma unroll
    for (int o = 16; o > 0; o >>= 1) v += __shfl_xor_sync(0xffffffffu, v, o);
    if (lane == 0) red[wrp] = v;
    __syncthreads();
    if (tid < 32) {
        float x = red[tid];
#pragma unroll
        for (int o = 16; o > 0; o >>= 1) x += __shfl_xor_sync(0xffffffffu, x, o);
        if (tid == 0) red[32] = x;
    }
    __syncthreads();
    float Teff = red[32];

    // --- max ---
    v = fmaxf(fmaxf(sm[0], sm[1]), fmaxf(sm[2], sm[3]));
#pragma unroll
    for (int o = 16; o > 0; o >>= 1) v = fmaxf(v, __shfl_xor_sync(0xffffffffu, v, o));
    if (lane == 0) red[wrp] = v;
    __syncthreads();
    if (tid < 32) {
        float x = red[tid];
#pragma unroll
        for (int o = 16; o > 0; o >>= 1) x = fmaxf(x, __shfl_xor_sync(0xffffffffu, x, o));
        if (tid == 0) red[32] = x;
    }
    __syncthreads();
    float M = red[32];

    // --- exp + Z ---
    float e[4];
    float es = 0.f;
#pragma unroll
    for (int i = 0; i < 4; ++i) { e[i] = expf(sm[i] - M); es += e[i]; }
    v = es;
#pragma unroll
    for (int o = 16; o > 0; o >>= 1) v += __shfl_xor_sync(0xffffffffu, v, o);
    if (lane == 0) red[wrp] = v;
    __syncthreads();
    if (tid < 32) {
        float x = red[tid];
#pragma unroll
        for (int o = 16; o > 0; o >>= 1) x += __shfl_xor_sync(0xffffffffu, x, o);
        if (tid == 0) red[32] = x;
    }
    __syncthreads();
    float Z = red[32];

    float K = fmaxf(1.f, rintf(0.2f * Teff));
    float entl = 0.f;
#pragma unroll
    for (int i = 0; i < 4; ++i) {
        int t = tid + 1024 * i;
        float p = e[i] / Z;
        float z = K * p;
        out[ROWS + b * Tn + t] = z;
        zbits[t] = __float_as_uint(z);      // z >= 0: bit order == value order
        entl -= p * logf(p + 1e-12f);
    }
    // --- entropy sum ---
    v = entl;
#pragma unroll
    for (int o = 16; o > 0; o >>= 1) v += __shfl_xor_sync(0xffffffffu, v, o);
    if (lane == 0) red[wrp] = v;
    __syncthreads();
    if (tid < 32) {
        float x = red[tid];
#pragma unroll
        for (int o = 16; o > 0; o >>= 1) x += __shfl_xor_sync(0xffffffffu, x, o);
        if (tid == 0) g_ent[b] = x / logf(fmaxf(Teff, 1.f));
    }
    __syncthreads();

    // ---- radix-select top-K on zbits (exact, stable) ----
    uint32_t krem = (uint32_t)K;
    uint32_t prefix = 0, mask = 0;
#pragma unroll
    for (int lvl = 3; lvl >= 0; --lvl) {
        if (tid < 256) hist[tid] = 0;
        __syncthreads();
        int sh = lvl * 8;
#pragma unroll
        for (int i = 0; i < 4; ++i) {
            uint32_t w = zbits[tid + 1024 * i];
            if ((w & mask) == prefix) atomicAdd(&hist[(w >> sh) & 255u], 1u);
        }
        __syncthreads();
        // warp-0 suffix-scan digit select: find largest d with suffix_sum(d) >= krem
        if (tid < 32) {
            uint32_t h[8]; uint32_t loc = 0;
#pragma unroll
            for (int jj = 0; jj < 8; ++jj) { h[jj] = hist[tid * 8 + jj]; loc += h[jj]; }
            uint32_t suf = loc;
#pragma unroll
            for (int o = 1; o < 32; o <<= 1) {
                uint32_t tt = __shfl_down_sync(0xffffffffu, suf, o);
                if (tid + o < 32) suf += tt;
            }
            uint32_t sufNext = suf - loc;   // suffix at bin 8*(tid+1)
            if (suf >= krem && sufNext < krem) {
                uint32_t pre = 0; int dj = 0; uint32_t sj = suf;
#pragma unroll
                for (int jj = 0; jj < 8; ++jj) {
                    uint32_t sfx = suf - pre;
                    if (sfx >= krem) { dj = jj; sj = sfx; }
                    pre += h[jj];
                }
                bcast[0] = (uint32_t)(tid * 8 + dj);
                bcast[1] = krem - (sj - h[dj]);   // krem - suffix(d+1)
            }
        }
        __syncthreads();
        uint32_t d = bcast[0]; krem = bcast[1];
        prefix |= d << sh; mask |= 255u << sh;
        __syncthreads();
    }
    uint32_t vth = prefix;

    // stable tiebreak: exclusive prefix count of (z == v) in index order (warp scan)
    uint32_t ev[4]; uint32_t eqc = 0;
#pragma unroll
    for (int jj = 0; jj < 4; ++jj) { ev[jj] = zbits[tid * 4 + jj]; eqc += (ev[jj] == vth); }
    uint32_t sc = eqc;
#pragma unroll
    for (int o = 1; o < 32; o <<= 1) {
        uint32_t tt = __shfl_up_sync(0xffffffffu, sc, o);
        if (lane >= o) sc += tt;
    }
    if (lane == 31) iscan[wrp] = sc;     // warp inclusive totals
    __syncthreads();
    if (tid < 32) {
        uint32_t x = iscan[tid];
#pragma unroll
        for (int o = 1; o < 32; o <<= 1) {
            uint32_t tt = __shfl_up_sync(0xffffffffu, x, o);
            if (tid >= o) x += tt;
        }
        iscan[tid] = x;                  // inclusive scan of warp totals
    }
    __syncthreads();
    uint32_t woff = (wrp == 0) ? 0u : iscan[wrp - 1];
    uint32_t run = woff + sc - eqc;      // exclusive prefix for this thread

    float* dst = out + (size_t)b * Tn;
#pragma unroll
    for (int jj = 0; jj < 4; ++jj) {
        uint32_t z = ev[jj];
        bool h = (z > vth) || (z == vth && run < krem);
        run += (z == vth);
        dst[tid * 4 + jj] = h ? 1.f : 0.f;
    }

    // deterministic norm_entropy: last block to finish sums g_ent in fixed order
    if (tid == 0) {
        __threadfence();
        int t = atomicAdd(&g_ticket, 1);
        if (t == Bn - 1) {
            float s = 0.f;
#pragma unroll
            for (int i = 0; i < Bn; ++i) s += g_ent[i];
            out[2 * ROWS] = s * (1.f / Bn);
        }
    }
}

// ---------------- launch ----------------
extern "C" void kernel_launch(void* const* d_in, const int* in_sizes, int n_in,
                              void* d_out, int out_size)
{
    const float* emb  = (const float*)d_in[0];
    const float* attn = (const float*)d_in[1];
    const float* lnw  = (const float*)d_in[2];
    const float* lnb  = (const float*)d_in[3];
    const float* w1   = (const float*)d_in[4];
    const float* b1   = (const float*)d_in[5];
    const float* w2   = (const float*)d_in[6];
    const float* b2   = (const float*)d_in[7];
    float* out = (float*)d_out;

    static int smem_set = 0;
    if (!smem_set) {
        cudaFuncSetAttribute(gemm_kernel, cudaFuncAttributeMaxDynamicSharedMemorySize, SMEM_REQ);
        smem_set = 1;
    }

    combo_kernel<<<ROWS / 8 + NPAD, 256>>>(emb, attn, w1, b1, w2, lnw, lnb);
    dim3 gg(NT, ROWS / 128);
    gemm_kernel<<<gg, 256, SMEM_REQ>>>(emb);
    final_kernel<<<Bn, 1024>>>(attn, b2, out);
}

// round 15
// speedup vs baseline: 1.3476x; 1.0108x over previous
#include <cuda_runtime.h>
#include <cuda_fp16.h>
#include <math.h>
#include <stdint.h>

#define Bn 16
#define Tn 4096
#define Dn 1024
#define HIDn 1365
#define NPAD 1408
#define ROWS (Bn*Tn)       // 65536
#define NT 11              // N tiles of 128

#define NPREP NPAD         // 1408 prep blocks
#define NSTAT 128          // stats blocks (512 rows each)
#define GOFF (NPREP + NSTAT)
#define NGEMM (NT * (ROWS/128))   // 5632
#define NCTAS (GOFF + NGEMM)      // 7168

// ---------------- scratch ----------------
__device__ float g_s[ROWS];
__device__ float g_cb[ROWS];
__device__ float g_Bp[(size_t)NPAD * Dn];   // lnw * w1, padded with zeros
__device__ float g_u[NPAD];
__device__ float g_bb[NPAD];
__device__ float g_w2p[NPAD];
__device__ float g_part[(size_t)NT * ROWS];
__device__ float g_ent[Bn];
__device__ int   g_ticket;
__device__ int   g_prep_done;
__device__ int   g_stats_done;

// ---------------- SMEM layout (bytes) ----------------
#define STRDB 48                 // row stride: 32B data (16 halves) + 16B pad
#define MATB (128 * STRDB)       // 6144 per matrix
#define S_AHI 0
#define S_ALO (MATB)
#define S_BHI (2*MATB)
#define S_BLO (3*MATB)
#define STAGEB (4*MATB)          // 24576
#define S_EPI (2*STAGEB)         // 49152 (128*16B)
#define S_RED (S_EPI + 2048)
#define SMEM_REQ (S_RED + 2048)  // 53248

// ---------------- helpers ----------------
__device__ __forceinline__ void sts128(uint32_t addr, uint32_t a, uint32_t b, uint32_t c, uint32_t d) {
    asm volatile("st.shared.v4.b32 [%0], {%1,%2,%3,%4};" :: "r"(addr), "r"(a), "r"(b), "r"(c), "r"(d));
}
__device__ __forceinline__ void stsf(uint32_t addr, float v) {
    asm volatile("st.shared.f32 [%0], %1;" :: "r"(addr), "f"(v));
}
__device__ __forceinline__ void lds4f(uint32_t addr, float& a, float& b, float& c, float& d) {
    asm volatile("ld.shared.v4.f32 {%0,%1,%2,%3}, [%4];"
                 : "=f"(a), "=f"(b), "=f"(c), "=f"(d) : "r"(addr));
}
__device__ __forceinline__ void sts4f(uint32_t addr, float a, float b, float c, float d) {
    asm volatile("st.shared.v4.f32 [%0], {%1,%2,%3,%4};"
                 :: "r"(addr), "f"(a), "f"(b), "f"(c), "f"(d));
}
__device__ __forceinline__ void ldsm4(uint32_t r[4], uint32_t addr) {
    asm volatile("ldmatrix.sync.aligned.m8n8.x4.shared.b16 {%0,%1,%2,%3}, [%4];"
                 : "=r"(r[0]), "=r"(r[1]), "=r"(r[2]), "=r"(r[3]) : "r"(addr));
}
__device__ __forceinline__ void mma16(float c[4], const uint32_t a[4], const uint32_t b[2]) {
    asm("mma.sync.aligned.m16n8k16.row.col.f32.f16.f16.f32 "
        "{%0,%1,%2,%3}, {%4,%5,%6,%7}, {%8,%9}, {%0,%1,%2,%3};"
        : "+f"(c[0]), "+f"(c[1]), "+f"(c[2]), "+f"(c[3])
        : "r"(a[0]), "r"(a[1]), "r"(a[2]), "r"(a[3]), "r"(b[0]), "r"(b[1]));
}
// split two floats into packed fp16 hi pair + lo pair
__device__ __forceinline__ void split2(float a, float b, uint32_t& hi, uint32_t& lo) {
    __half ha = __float2half_rn(a), hb = __float2half_rn(b);
    float ra = a - __half2float(ha);
    float rb = b - __half2float(hb);
    __half la = __float2half_rn(ra), lb = __float2half_rn(rb);
    hi = (uint32_t)__half_as_ushort(ha) | ((uint32_t)__half_as_ushort(hb) << 16);
    lo = (uint32_t)__half_as_ushort(la) | ((uint32_t)__half_as_ushort(lb) << 16);
}
// convert 8 floats (one 16B chunk of one row) -> hi sts128 + lo sts128 (lo at +MATB)
__device__ __forceinline__ void cvtstore(uint32_t hiAddr, float4 v0, float4 v1) {
    uint32_t h0,h1,h2,h3,l0,l1,l2,l3;
    split2(v0.x, v0.y, h0, l0); split2(v0.z, v0.w, h1, l1);
    split2(v1.x, v1.y, h2, l2); split2(v1.z, v1.w, h3, l3);
    sts128(hiAddr,        h0, h1, h2, h3);
    sts128(hiAddr + MATB, l0, l1, l2, l3);
}

// ---------------- kernel 0: fused prep + stats + gemm (flag-gated) ----------------
__global__ __launch_bounds__(256, 2) void mega_kernel(
    const float* __restrict__ emb, const float* __restrict__ attn,
    const float* __restrict__ w1, const float* __restrict__ b1,
    const float* __restrict__ w2, const float* __restrict__ lnw,
    const float* __restrict__ lnb)
{
    extern __shared__ char smraw[];
    int bid = blockIdx.x;
    int tid = threadIdx.x;

    if (bid < NPREP) {
        // ======== prep: B' = lnw*w1 (padded), u, bb, w2p ========
        __shared__ float ru[8], rv[8];
        int n = bid;
        if (n < HIDn) {
            float4 w  = ((const float4*)(w1 + (size_t)n * Dn))[tid];
            float4 lw = ((const float4*)lnw)[tid];
            float4 lb = ((const float4*)lnb)[tid];
            float4 bp;
            bp.x = lw.x * w.x; bp.y = lw.y * w.y; bp.z = lw.z * w.z; bp.w = lw.w * w.w;
            ((float4*)(g_Bp + (size_t)n * Dn))[tid] = bp;
            float up = bp.x + bp.y + bp.z + bp.w;
            float vp = lb.x*w.x + lb.y*w.y + lb.z*w.z + lb.w*w.w;
#pragma unroll
            for (int o = 16; o > 0; o >>= 1) {
                up += __shfl_xor_sync(0xffffffffu, up, o);
                vp += __shfl_xor_sync(0xffffffffu, vp, o);
            }
            if ((tid & 31) == 0) { ru[tid >> 5] = up; rv[tid >> 5] = vp; }
            __syncthreads();
            if (tid == 0) {
                float u = 0.f, v = 0.f;
#pragma unroll
                for (int i = 0; i < 8; ++i) { u += ru[i]; v += rv[i]; }
                g_u[n]   = u;
                g_bb[n]  = b1[n] + v;
                g_w2p[n] = w2[n];
            }
        } else {
            ((float4*)(g_Bp + (size_t)n * Dn))[tid] = make_float4(0.f, 0.f, 0.f, 0.f);
            if (tid == 0) { g_u[n] = 0.f; g_bb[n] = 0.f; g_w2p[n] = 0.f; }
        }
        __syncthreads();
        if (tid == 0) { __threadfence(); atomicAdd(&g_prep_done, 1); }
        return;
    }

    if (bid < GOFF) {
        // ======== stats: per-row LN stats -> s, cb (512 rows per block) ========
        int sbid = bid - NPREP;
        int lane = tid & 31;
        int wrp  = tid >> 5;
        int base = sbid * 512 + wrp * 64;
        for (int r = 0; r < 64; ++r) {
            int row = base + r;
            const float4* p = (const float4*)(emb + (size_t)row * Dn);
            float a = attn[row];
            float s = 0.f, q = 0.f;
#pragma unroll
            for (int i = 0; i < 8; ++i) {
                float4 v = p[lane + 32 * i];
                v.x *= a; v.y *= a; v.z *= a; v.w *= a;
                s += v.x + v.y + v.z + v.w;
                q += v.x*v.x + v.y*v.y + v.z*v.z + v.w*v.w;
            }
#pragma unroll
            for (int o = 16; o > 0; o >>= 1) {
                s += __shfl_xor_sync(0xffffffffu, s, o);
                q += __shfl_xor_sync(0xffffffffu, q, o);
            }
            if (lane == 0) {
                float mu  = s * (1.f / Dn);
                float var = fmaxf(q * (1.f / Dn) - mu * mu, 0.f);
                float rs  = rsqrtf(var + 1e-5f);
                g_s[row]  = a * rs;
                g_cb[row] = -mu * rs;
            }
        }
        __syncthreads();
        if (tid == 0) { __threadfence(); atomicAdd(&g_stats_done, 1); }
        return;
    }

    // ======== gemm: fp16x3 mma.sync (round-14 core) ========
    uint32_t sb = (uint32_t)__cvta_generic_to_shared(smraw);
    int gbid = bid - GOFF;
    int m0  = (gbid / NT) * 128;
    int n0  = (gbid % NT) * 128;

    // wait for prep (g_Bp needed from iteration 0)
    if (tid == 0) {
        volatile int* p = &g_prep_done;
        while (*p != NPREP) { }
    }
    __syncthreads();

    int wid = tid >> 5;
    int l   = tid & 31;
    int wm  = (wid >> 2) * 64;       // 0 or 64
    int wn  = (wid & 3) * 32;        // 0,32,64,96

    int lrow = tid >> 1;
    int lc   = tid & 1;
    const float* aP = emb  + (size_t)(m0 + lrow) * Dn + lc * 8;
    const float* bP = g_Bp + (size_t)(n0 + lrow) * Dn + lc * 8;
    uint32_t sA = sb + S_AHI + (uint32_t)lrow * STRDB + (uint32_t)lc * 16;
    uint32_t sB = sb + S_BHI + (uint32_t)lrow * STRDB + (uint32_t)lc * 16;

    int g = l >> 3, j = l & 7;
    uint32_t aAddr0 = sb + S_AHI
        + (uint32_t)(wm + ((g & 1) ? 8 : 0) + j) * STRDB + (uint32_t)(g >> 1) * 16;
    uint32_t bAddr0 = sb + S_BHI
        + (uint32_t)(wn + ((g >> 1) ? 8 : 0) + j) * STRDB + (uint32_t)(g & 1) * 16;

    float acc[4][4][4];
#pragma unroll
    for (int mi = 0; mi < 4; ++mi)
#pragma unroll
        for (int nf = 0; nf < 4; ++nf)
#pragma unroll
            for (int e = 0; e < 4; ++e) acc[mi][nf][e] = 0.f;

    float4 pa0 = ((const float4*)aP)[0], pa1 = ((const float4*)aP)[1];
    float4 pb0 = ((const float4*)bP)[0], pb1 = ((const float4*)bP)[1];
    cvtstore(sA, pa0, pa1);
    cvtstore(sB, pb0, pb1);
    __syncthreads();

    for (int it = 0; it < 64; ++it) {
        uint32_t so = (uint32_t)(it & 1) * STAGEB;
        if (it < 63) {
            int kc = (it + 1) * 16;
            pa0 = ((const float4*)(aP + kc))[0]; pa1 = ((const float4*)(aP + kc))[1];
            pb0 = ((const float4*)(bP + kc))[0]; pb1 = ((const float4*)(bP + kc))[1];
        }
        uint32_t bh[4][2], bl[4][2];
#pragma unroll
        for (int p = 0; p < 2; ++p) {
            uint32_t r[4];
            uint32_t ba = bAddr0 + (uint32_t)p * (16 * STRDB) + so;
            ldsm4(r, ba);
            bh[2*p][0] = r[0]; bh[2*p][1] = r[1]; bh[2*p+1][0] = r[2]; bh[2*p+1][1] = r[3];
            ldsm4(r, ba + MATB);
            bl[2*p][0] = r[0]; bl[2*p][1] = r[1]; bl[2*p+1][0] = r[2]; bl[2*p+1][1] = r[3];
        }
#pragma unroll
        for (int mi = 0; mi < 4; ++mi) {
            uint32_t ah[4], al[4];
            uint32_t aa = aAddr0 + (uint32_t)mi * (16 * STRDB) + so;
            ldsm4(ah, aa);
            ldsm4(al, aa + MATB);
#pragma unroll
            for (int nf = 0; nf < 4; ++nf) mma16(acc[mi][nf], ah, bh[nf]);
#pragma unroll
            for (int nf = 0; nf < 4; ++nf) mma16(acc[mi][nf], al, bh[nf]);
#pragma unroll
            for (int nf = 0; nf < 4; ++nf) mma16(acc[mi][nf], ah, bl[nf]);
        }
        if (it < 63) {
            uint32_t ns = (uint32_t)((it + 1) & 1) * STAGEB;
            cvtstore(sA + ns, pa0, pa1);
            cvtstore(sB + ns, pb0, pb1);
        }
        __syncthreads();
    }

    // wait for stats (g_s/g_cb needed below)
    if (tid == 0) {
        volatile int* p = &g_stats_done;
        while (*p != NSTAT) { }
    }
    if (tid < 128) {
        int n = n0 + tid;
        sts4f(sb + S_EPI + (uint32_t)tid * 16, g_u[n], g_bb[n], g_w2p[n], 0.f);
    }
    __syncthreads();

    int lg = l >> 2;
    int lt = l & 3;

    float uu[8], bbv[8], w2v[8];
#pragma unroll
    for (int nf = 0; nf < 4; ++nf) {
#pragma unroll
        for (int e = 0; e < 2; ++e) {
            int nl = wn + nf * 8 + 2 * lt + e;
            float pad;
            lds4f(sb + S_EPI + (uint32_t)nl * 16, uu[nf*2+e], bbv[nf*2+e], w2v[nf*2+e], pad);
        }
    }

    const float GC = 0.70710678118654752440f;
#pragma unroll
    for (int mi = 0; mi < 4; ++mi) {
        int r0 = wm + mi * 16 + lg;
        int r1 = r0 + 8;
        float s0 = g_s[m0 + r0], c0 = g_cb[m0 + r0];
        float s1 = g_s[m0 + r1], c1 = g_cb[m0 + r1];
        float sum0 = 0.f, sum1 = 0.f;
#pragma unroll
        for (int nf = 0; nf < 4; ++nf) {
#pragma unroll
            for (int e = 0; e < 2; ++e) {
                int jj = nf * 2 + e;
                float x0 = fmaf(s0, acc[mi][nf][e],     fmaf(c0, uu[jj], bbv[jj]));
                float x1 = fmaf(s1, acc[mi][nf][e + 2], fmaf(c1, uu[jj], bbv[jj]));
                float gl0 = 0.5f * x0 * (1.f + erff(x0 * GC));
                float gl1 = 0.5f * x1 * (1.f + erff(x1 * GC));
                sum0 = fmaf(gl0, w2v[jj], sum0);
                sum1 = fmaf(gl1, w2v[jj], sum1);
            }
        }
        sum0 += __shfl_xor_sync(0xffffffffu, sum0, 1);
        sum0 += __shfl_xor_sync(0xffffffffu, sum0, 2);
        sum1 += __shfl_xor_sync(0xffffffffu, sum1, 1);
        sum1 += __shfl_xor_sync(0xffffffffu, sum1, 2);
        if (lt == 0) {
            stsf(sb + S_RED + (uint32_t)(r0 * 4 + (wid & 3)) * 4, sum0);
            stsf(sb + S_RED + (uint32_t)(r1 * 4 + (wid & 3)) * 4, sum1);
        }
    }
    __syncthreads();
    if (tid < 128) {
        uint32_t ra = sb + S_RED + (uint32_t)tid * 16;
        float a, b, c, d; lds4f(ra, a, b, c, d);
        g_part[(size_t)(gbid % NT) * ROWS + m0 + tid] = ((a + b) + c) + d;
    }
}

// ---------------- kernel 1: reduce + softmax/entropy/K/z + radix top-K (round-14) ----------------
__global__ __launch_bounds__(1024) void final_kernel(
    const float* __restrict__ attn, const float* __restrict__ fc2_b,
    float* __restrict__ out)
{
    __shared__ float red[33];
    __shared__ uint32_t zbits[Tn];
    __shared__ uint32_t hist[256];
    __shared__ uint32_t bcast[2];
    __shared__ uint32_t iscan[32];
    int b = blockIdx.x, tid = threadIdx.x;
    int lane = tid & 31, wrp = tid >> 5;
    float base = fc2_b[0];

    float a[4], sm[4];
#pragma unroll
    for (int i = 0; i < 4; ++i) {
        int t = tid + 1024 * i;
        float s = base;
#pragma unroll
        for (int nt = 0; nt < NT; ++nt) s += g_part[(size_t)nt * ROWS + b * Tn + t];
        a[i]  = attn[b * Tn + t];
        sm[i] = (a[i] == 0.f) ? -1e9f : s;
    }

    float v = a[0] + a[1] + a[2] + a[3];
#pragma unroll
    for (int o = 16; o > 0; o >>= 1) v += __shfl_xor_sync(0xffffffffu, v, o);
    if (lane == 0) red[wrp] = v;
    __syncthreads();
    if (tid < 32) {
        float x = red[tid];
#pragma unroll
        for (int o = 16; o > 0; o >>= 1) x += __shfl_xor_sync(0xffffffffu, x, o);
        if (tid == 0) red[32] = x;
    }
    __syncthreads();
    float Teff = red[32];

    v = fmaxf(fmaxf(sm[0], sm[1]), fmaxf(sm[2], sm[3]));
#pragma unroll
    for (int o = 16; o > 0; o >>= 1) v = fmaxf(v, __shfl_xor_sync(0xffffffffu, v, o));
    if (lane == 0) red[wrp] = v;
    __syncthreads();
    if (tid < 32) {
        float x = red[tid];
#pragma unroll
        for (int o = 16; o > 0; o >>= 1) x = fmaxf(x, __shfl_xor_sync(0xffffffffu, x, o));
        if (tid == 0) red[32] = x;
    }
    __syncthreads();
    float M = red[32];

    float e[4];
    float es = 0.f;
#pragma unroll
    for (int i = 0; i < 4; ++i) { e[i] = expf(sm[i] - M); es += e[i]; }
    v = es;
#pragma unroll
    for (int o = 16; o > 0; o >>= 1) v += __shfl_xor_sync(0xffffffffu, v, o);
    if (lane == 0) red[wrp] = v;
    __syncthreads();
    if (tid < 32) {
        float x = red[tid];
#pragma unroll
        for (int o = 16; o > 0; o >>= 1) x += __shfl_xor_sync(0xffffffffu, x, o);
        if (tid == 0) red[32] = x;
    }
    __syncthreads();
    float Z = red[32];

    float K = fmaxf(1.f, rintf(0.2f * Teff));
    float entl = 0.f;
#pragma unroll
    for (int i = 0; i < 4; ++i) {
        int t = tid + 1024 * i;
        float p = e[i] / Z;
        float z = K * p;
        out[ROWS + b * Tn + t] = z;
        zbits[t] = __float_as_uint(z);
        entl -= p * logf(p + 1e-12f);
    }
    v = entl;
#pragma unroll
    for (int o = 16; o > 0; o >>= 1) v += __shfl_xor_sync(0xffffffffu, v, o);
    if (lane == 0) red[wrp] = v;
    __syncthreads();
    if (tid < 32) {
        float x = red[tid];
#pragma unroll
        for (int o = 16; o > 0; o >>= 1) x += __shfl_xor_sync(0xffffffffu, x, o);
        if (tid == 0) g_ent[b] = x / logf(fmaxf(Teff, 1.f));
    }
    __syncthreads();

    uint32_t krem = (uint32_t)K;
    uint32_t prefix = 0, mask = 0;
#pragma unroll
    for (int lvl = 3; lvl >= 0; --lvl) {
        if (tid < 256) hist[tid] = 0;
        __syncthreads();
        int sh = lvl * 8;
#pragma unroll
        for (int i = 0; i < 4; ++i) {
            uint32_t w = zbits[tid + 1024 * i];
            if ((w & mask) == prefix) atomicAdd(&hist[(w >> sh) & 255u], 1u);
        }
        __syncthreads();
        if (tid < 32) {
            uint32_t h[8]; uint32_t loc = 0;
#pragma unroll
            for (int jj = 0; jj < 8; ++jj) { h[jj] = hist[tid * 8 + jj]; loc += h[jj]; }
            uint32_t suf = loc;
#pragma unroll
            for (int o = 1; o < 32; o <<= 1) {
                uint32_t tt = __shfl_down_sync(0xffffffffu, suf, o);
                if (tid + o < 32) suf += tt;
            }
            uint32_t sufNext = suf - loc;
            if (suf >= krem && sufNext < krem) {
                uint32_t pre = 0; int dj = 0; uint32_t sj = suf;
#pragma unroll
                for (int jj = 0; jj < 8; ++jj) {
                    uint32_t sfx = suf - pre;
                    if (sfx >= krem) { dj = jj; sj = sfx; }
                    pre += h[jj];
                }
                bcast[0] = (uint32_t)(tid * 8 + dj);
                bcast[1] = krem - (sj - h[dj]);
            }
        }
        __syncthreads();
        uint32_t d = bcast[0]; krem = bcast[1];
        prefix |= d << sh; mask |= 255u << sh;
        __syncthreads();
    }
    uint32_t vth = prefix;

    uint32_t ev[4]; uint32_t eqc = 0;
#pragma unroll
    for (int jj = 0; jj < 4; ++jj) { ev[jj] = zbits[tid * 4 + jj]; eqc += (ev[jj] == vth); }
    uint32_t sc = eqc;
#pragma unroll
    for (int o = 1; o < 32; o <<= 1) {
        uint32_t tt = __shfl_up_sync(0xffffffffu, sc, o);
        if (lane >= o) sc += tt;
    }
    if (lane == 31) iscan[wrp] = sc;
    __syncthreads();
    if (tid < 32) {
        uint32_t x = iscan[tid];
#pragma unroll
        for (int o = 1; o < 32; o <<= 1) {
            uint32_t tt = __shfl_up_sync(0xffffffffu, x, o);
            if (tid >= o) x += tt;
        }
        iscan[tid] = x;
    }
    __syncthreads();
    uint32_t woff = (wrp == 0) ? 0u : iscan[wrp - 1];
    uint32_t run = woff + sc - eqc;

    float* dst = out + (size_t)b * Tn;
#pragma unroll
    for (int jj = 0; jj < 4; ++jj) {
        uint32_t z = ev[jj];
        bool h = (z > vth) || (z == vth && run < krem);
        run += (z == vth);
        dst[tid * 4 + jj] = h ? 1.f : 0.f;
    }

    if (tid == 0) {
        __threadfence();
        int t = atomicAdd(&g_ticket, 1);
        if (t == Bn - 1) {
            float s = 0.f;
#pragma unroll
            for (int i = 0; i < Bn; ++i) s += g_ent[i];
            out[2 * ROWS] = s * (1.f / Bn);
            // reset flags for the next (graph-replayed) invocation
            g_ticket = 0;
            g_prep_done = 0;
            g_stats_done = 0;
        }
    }
}

// ---------------- launch ----------------
extern "C" void kernel_launch(void* const* d_in, const int* in_sizes, int n_in,
                              void* d_out, int out_size)
{
    const float* emb  = (const float*)d_in[0];
    const float* attn = (const float*)d_in[1];
    const float* lnw  = (const float*)d_in[2];
    const float* lnb  = (const float*)d_in[3];
    const float* w1   = (const float*)d_in[4];
    const float* b1   = (const float*)d_in[5];
    const float* w2   = (const float*)d_in[6];
    const float* b2   = (const float*)d_in[7];
    float* out = (float*)d_out;

    static int smem_set = 0;
    if (!smem_set) {
        cudaFuncSetAttribute(mega_kernel, cudaFuncAttributeMaxDynamicSharedMemorySize, SMEM_REQ);
        smem_set = 1;
    }

    mega_kernel<<<NCTAS, 256, SMEM_REQ>>>(emb, attn, w1, b1, w2, lnw, lnb);
    final_kernel<<<Bn, 1024>>>(attn, b2, out);
}